// round 1
// baseline (speedup 1.0000x reference)
#include <cuda_runtime.h>
#include <math.h>

#define BB   2
#define SS   2048
#define DD   768
#define HH   12
#define DKK  64

// Scratch (allocation-free): head-split projections + attention context
__device__ float g_q[(size_t)BB * HH * SS * DKK];
__device__ float g_k[(size_t)BB * HH * SS * DKK];
__device__ float g_v[(size_t)BB * HH * SS * DKK];
__device__ float g_ctx[(size_t)BB * SS * DD];

// ---------------------------------------------------------------------------
// GEMM: C[M,N] = A[M,K] * W[N,K]^T   (torch Linear: x @ W.T)
//   MODE 0: projections.  A selected from {Q,K,V} by blockIdx.z, W from
//           {Wq,Wk,Wv}.  Epilogue writes head-split [b][h][s][dk] into
//           g_q / g_k / g_v.
//   MODE 1: output proj.  A = g_ctx, W = w0 (Wo).  Plain [n][col] epilogue.
// 128x128 tile, BK=16, 256 threads, 8x8 per-thread micro-tile.
// ---------------------------------------------------------------------------
template<int MODE>
__global__ __launch_bounds__(256)
void gemm_kernel(const float* __restrict__ x0, const float* __restrict__ x1,
                 const float* __restrict__ x2, const float* __restrict__ w0,
                 const float* __restrict__ w1, const float* __restrict__ w2,
                 float* __restrict__ outp)
{
    constexpr int BM = 128, BN = 128, BK = 16;
    __shared__ float As[BK][BM + 4];
    __shared__ float Bs[BK][BN + 4];

    const float* X;
    const float* W;
    if (MODE == 0) {
        X = (blockIdx.z == 0) ? x0 : (blockIdx.z == 1) ? x1 : x2;
        W = (blockIdx.z == 0) ? w0 : (blockIdx.z == 1) ? w1 : w2;
    } else {
        X = g_ctx;
        W = w0;
    }

    const int tid     = threadIdx.x;
    const int rowBase = blockIdx.y * BM;
    const int colBase = blockIdx.x * BN;
    const int ty      = tid >> 4;    // 0..15 (M direction, 8 rows each)
    const int tx      = tid & 15;    // 0..15 (N direction, 8 cols each)

    float acc[8][8];
    #pragma unroll
    for (int i = 0; i < 8; ++i)
        #pragma unroll
        for (int j = 0; j < 8; ++j) acc[i][j] = 0.f;

    for (int k0 = 0; k0 < DD; k0 += BK) {
        // Load 128x16 A tile and 128x16 W tile (transposed into smem)
        #pragma unroll
        for (int it = 0; it < 2; ++it) {
            int idx = tid + it * 256;       // 0..511
            int r   = idx >> 2;             // 0..127
            int c4  = (idx & 3) * 4;        // 0,4,8,12
            float4 av = *(const float4*)(X + (size_t)(rowBase + r) * DD + k0 + c4);
            As[c4 + 0][r] = av.x; As[c4 + 1][r] = av.y;
            As[c4 + 2][r] = av.z; As[c4 + 3][r] = av.w;
            float4 bv = *(const float4*)(W + (size_t)(colBase + r) * DD + k0 + c4);
            Bs[c4 + 0][r] = bv.x; Bs[c4 + 1][r] = bv.y;
            Bs[c4 + 2][r] = bv.z; Bs[c4 + 3][r] = bv.w;
        }
        __syncthreads();

        #pragma unroll
        for (int k = 0; k < BK; ++k) {
            float a[8], bfr[8];
            *(float4*)&a[0]   = *(const float4*)&As[k][ty * 8];
            *(float4*)&a[4]   = *(const float4*)&As[k][ty * 8 + 4];
            *(float4*)&bfr[0] = *(const float4*)&Bs[k][tx * 8];
            *(float4*)&bfr[4] = *(const float4*)&Bs[k][tx * 8 + 4];
            #pragma unroll
            for (int i = 0; i < 8; ++i)
                #pragma unroll
                for (int j = 0; j < 8; ++j)
                    acc[i][j] += a[i] * bfr[j];
        }
        __syncthreads();
    }

    if (MODE == 0) {
        float* dst = (blockIdx.z == 0) ? g_q : (blockIdx.z == 1) ? g_k : g_v;
        #pragma unroll
        for (int i = 0; i < 8; ++i) {
            int n = rowBase + ty * 8 + i;
            int b = n >> 11;            // /2048
            int s = n & (SS - 1);
            #pragma unroll
            for (int j = 0; j < 8; ++j) {
                int col = colBase + tx * 8 + j;
                int h   = col >> 6;
                int dd  = col & 63;
                dst[(((size_t)b * HH + h) * SS + s) * DKK + dd] = acc[i][j];
            }
        }
    } else {
        #pragma unroll
        for (int i = 0; i < 8; ++i) {
            int n = rowBase + ty * 8 + i;
            #pragma unroll
            for (int j = 0; j < 8; ++j)
                outp[(size_t)n * DD + colBase + tx * 8 + j] = acc[i][j];
        }
    }
}

// ---------------------------------------------------------------------------
// Causal flash attention: 1 thread = 1 query row.  128 rows / CTA.
// K/V tiles (64 keys x 64) staged in smem, read as broadcast LDS.128.
// Online softmax in 32-key chunks (scores kept in registers).
// blockIdx.x reversed so the heavy (late-q) blocks start first.
// ---------------------------------------------------------------------------
__global__ __launch_bounds__(128, 2)
void flash_kernel()
{
    const int b   = blockIdx.z;
    const int h   = blockIdx.y;
    const int qb  = (gridDim.x - 1) - blockIdx.x;
    const int tid = threadIdx.x;
    const int qi  = qb * 128 + tid;

    const size_t headOff = (size_t)(b * HH + h) * SS * DKK;
    const float* Qh = g_q + headOff;
    const float* Kh = g_k + headOff;
    const float* Vh = g_v + headOff;

    __shared__ float Ks[64][64];
    __shared__ float Vs[64][64];

    float q[64], o[64];
    #pragma unroll
    for (int d4 = 0; d4 < 16; ++d4) {
        float4 v = *(const float4*)(Qh + (size_t)qi * DKK + d4 * 4);
        q[d4 * 4 + 0] = v.x * 0.125f;   // 1/sqrt(64) folded into q
        q[d4 * 4 + 1] = v.y * 0.125f;
        q[d4 * 4 + 2] = v.z * 0.125f;
        q[d4 * 4 + 3] = v.w * 0.125f;
    }
    #pragma unroll
    for (int d = 0; d < 64; ++d) o[d] = 0.f;

    float m = -1e30f, l = 0.f;

    const int ntiles = 2 * (qb + 1);   // keys needed = (qb+1)*128, tile = 64
    for (int t = 0; t < ntiles; ++t) {
        const int kbase = t * 64;
        // Cooperative tile load: 64x64 floats each for K and V
        #pragma unroll
        for (int it = 0; it < 8; ++it) {
            int idx = tid + it * 128;      // 0..1023
            int r   = idx >> 4;            // 0..63
            int c4  = (idx & 15) * 4;      // 0..60
            *(float4*)&Ks[r][c4] = *(const float4*)(Kh + (size_t)(kbase + r) * DKK + c4);
            *(float4*)&Vs[r][c4] = *(const float4*)(Vh + (size_t)(kbase + r) * DKK + c4);
        }
        __syncthreads();

        #pragma unroll
        for (int cc = 0; cc < 2; ++cc) {
            const int base = cc * 32;
            float sc[32];
            float mnew = m;
            #pragma unroll
            for (int j = 0; j < 32; ++j) {
                float ssum = 0.f;
                #pragma unroll
                for (int d4 = 0; d4 < 16; ++d4) {
                    float4 kv = *(const float4*)&Ks[base + j][d4 * 4];
                    ssum += q[d4 * 4 + 0] * kv.x;
                    ssum += q[d4 * 4 + 1] * kv.y;
                    ssum += q[d4 * 4 + 2] * kv.z;
                    ssum += q[d4 * 4 + 3] * kv.w;
                }
                sc[j] = (kbase + base + j <= qi) ? ssum : -1e30f;
                mnew  = fmaxf(mnew, sc[j]);
            }
            float corr = __expf(m - mnew);
            m = mnew;
            l *= corr;
            #pragma unroll
            for (int d = 0; d < 64; ++d) o[d] *= corr;
            #pragma unroll
            for (int j = 0; j < 32; ++j) {
                float p = __expf(sc[j] - mnew);
                l += p;
                #pragma unroll
                for (int d4 = 0; d4 < 16; ++d4) {
                    float4 vv = *(const float4*)&Vs[base + j][d4 * 4];
                    o[d4 * 4 + 0] += p * vv.x;
                    o[d4 * 4 + 1] += p * vv.y;
                    o[d4 * 4 + 2] += p * vv.z;
                    o[d4 * 4 + 3] += p * vv.w;
                }
            }
        }
        __syncthreads();
    }

    const float inv = 1.0f / l;
    float* dst = g_ctx + ((size_t)b * SS + qi) * DD + h * DKK;
    #pragma unroll
    for (int d4 = 0; d4 < 16; ++d4) {
        float4 v;
        v.x = o[d4 * 4 + 0] * inv;
        v.y = o[d4 * 4 + 1] * inv;
        v.z = o[d4 * 4 + 2] * inv;
        v.w = o[d4 * 4 + 3] * inv;
        *(float4*)(dst + d4 * 4) = v;
    }
}

// ---------------------------------------------------------------------------
// Inputs (metadata order): Q, K, V, mask, Wq, Wk, Wv, Wo
// mask is exactly causal tril -> handled by the k<=q predicate; not read.
// ---------------------------------------------------------------------------
extern "C" void kernel_launch(void* const* d_in, const int* in_sizes, int n_in,
                              void* d_out, int out_size)
{
    (void)in_sizes; (void)n_in; (void)out_size;
    const float* Q  = (const float*)d_in[0];
    const float* K  = (const float*)d_in[1];
    const float* V  = (const float*)d_in[2];
    const float* Wq = (const float*)d_in[4];
    const float* Wk = (const float*)d_in[5];
    const float* Wv = (const float*)d_in[6];
    const float* Wo = (const float*)d_in[7];
    float* out = (float*)d_out;

    // 1) q/k/v projections (one launch, gridDim.z selects projection)
    gemm_kernel<0><<<dim3(DD / 128, (BB * SS) / 128, 3), 256>>>(
        Q, K, V, Wq, Wk, Wv, nullptr);

    // 2) causal flash attention -> g_ctx
    flash_kernel<<<dim3(SS / 128, HH, BB), 128>>>();

    // 3) output projection: out = ctx @ Wo^T
    gemm_kernel<1><<<dim3(DD / 128, (BB * SS) / 128, 1), 256>>>(
        nullptr, nullptr, nullptr, Wo, nullptr, nullptr, out);
}

// round 2
// speedup vs baseline: 1.5845x; 1.5845x over previous
#include <cuda_runtime.h>
#include <math.h>
#include <stdint.h>

#define BB   2
#define SS   2048
#define DD   768
#define HH   12
#define DKK  64

// Scratch (allocation-free)
__device__ float g_q[(size_t)BB * HH * SS * DKK];
__device__ float g_k[(size_t)BB * HH * SS * DKK];
__device__ float g_v[(size_t)BB * HH * SS * DKK];
__device__ float g_ctx[(size_t)BB * SS * DD];

// ---------------- packed f32x2 helpers (Blackwell FFMA2 path) ----------------
typedef unsigned long long u64;

__device__ __forceinline__ void ffma2(u64 &d, u64 a, u64 b) {
    asm volatile("fma.rn.f32x2 %0, %1, %2, %0;" : "+l"(d) : "l"(a), "l"(b));
}
__device__ __forceinline__ u64 mul2(u64 a, u64 b) {
    u64 r; asm("mul.rn.f32x2 %0, %1, %2;" : "=l"(r) : "l"(a), "l"(b)); return r;
}
__device__ __forceinline__ u64 pk2(float x, float y) {
    u64 r; asm("mov.b64 %0, {%1, %2};" : "=l"(r) : "f"(x), "f"(y)); return r;
}
__device__ __forceinline__ void upk2(u64 v, float &x, float &y) {
    asm("mov.b64 {%0, %1}, %2;" : "=f"(x), "=f"(y) : "l"(v));
}
__device__ __forceinline__ u64 lds64(uint32_t addr) {
    u64 v; asm volatile("ld.shared.b64 %0, [%1];" : "=l"(v) : "r"(addr)); return v;
}
__device__ __forceinline__ uint32_t smem_u32(const void* p) {
    return (uint32_t)__cvta_generic_to_shared(p);
}

// ---------------------------------------------------------------------------
// GEMM: C[M,N] = A[M,K] * W[N,K]^T  with packed FFMA2 (row-pair accumulators).
// MODE 0: q/k/v projections (blockIdx.z selects), head-split epilogue.
// MODE 1: output projection from g_ctx.
// 128x128 tile, BK=16, 256 threads, per-thread 8x8 (as 4 row-pairs x 8 cols).
// ---------------------------------------------------------------------------
template<int MODE>
__global__ __launch_bounds__(256)
void gemm_kernel(const float* __restrict__ x0, const float* __restrict__ x1,
                 const float* __restrict__ x2, const float* __restrict__ w0,
                 const float* __restrict__ w1, const float* __restrict__ w2,
                 float* __restrict__ outp)
{
    constexpr int BM = 128, BN = 128, BK = 16;
    __shared__ float As[BK][BM + 4];
    __shared__ float Bs[BK][BN + 4];

    const float* X;
    const float* W;
    if (MODE == 0) {
        X = (blockIdx.z == 0) ? x0 : (blockIdx.z == 1) ? x1 : x2;
        W = (blockIdx.z == 0) ? w0 : (blockIdx.z == 1) ? w1 : w2;
    } else {
        X = g_ctx;
        W = w0;
    }

    const int tid     = threadIdx.x;
    const int rowBase = blockIdx.y * BM;
    const int colBase = blockIdx.x * BN;
    const int ty      = tid >> 4;    // 0..15 -> 8 rows (4 row-pairs)
    const int tx      = tid & 15;    // 0..15 -> 8 cols

    u64 acc2[4][8];                  // [row-pair][col]: lo=row 2i, hi=row 2i+1
    #pragma unroll
    for (int i = 0; i < 4; ++i)
        #pragma unroll
        for (int j = 0; j < 8; ++j) acc2[i][j] = 0ull;

    const uint32_t aAddr = smem_u32(&As[0][ty * 8]);

    for (int k0 = 0; k0 < DD; k0 += BK) {
        #pragma unroll
        for (int it = 0; it < 2; ++it) {
            int idx = tid + it * 256;
            int r   = idx >> 2;
            int c4  = (idx & 3) * 4;
            float4 av = *(const float4*)(X + (size_t)(rowBase + r) * DD + k0 + c4);
            As[c4 + 0][r] = av.x; As[c4 + 1][r] = av.y;
            As[c4 + 2][r] = av.z; As[c4 + 3][r] = av.w;
            float4 bv = *(const float4*)(W + (size_t)(colBase + r) * DD + k0 + c4);
            Bs[c4 + 0][r] = bv.x; Bs[c4 + 1][r] = bv.y;
            Bs[c4 + 2][r] = bv.z; Bs[c4 + 3][r] = bv.w;
        }
        __syncthreads();

        #pragma unroll
        for (int k = 0; k < BK; ++k) {
            u64 a2[4];
            #pragma unroll
            for (int i = 0; i < 4; ++i)
                a2[i] = lds64(aAddr + (uint32_t)(k * (BM + 4) + 2 * i) * 4u);
            float bfr[8];
            *(float4*)&bfr[0] = *(const float4*)&Bs[k][tx * 8];
            *(float4*)&bfr[4] = *(const float4*)&Bs[k][tx * 8 + 4];
            u64 bb[8];
            #pragma unroll
            for (int j = 0; j < 8; ++j) bb[j] = pk2(bfr[j], bfr[j]);
            #pragma unroll
            for (int i = 0; i < 4; ++i)
                #pragma unroll
                for (int j = 0; j < 8; ++j)
                    ffma2(acc2[i][j], a2[i], bb[j]);
        }
        __syncthreads();
    }

    if (MODE == 0) {
        float* dst = (blockIdx.z == 0) ? g_q : (blockIdx.z == 1) ? g_k : g_v;
        #pragma unroll
        for (int i = 0; i < 4; ++i) {
            #pragma unroll
            for (int j = 0; j < 8; ++j) {
                float lo, hi;
                upk2(acc2[i][j], lo, hi);
                int col = colBase + tx * 8 + j;
                int h   = col >> 6;
                int dd  = col & 63;
                int n0  = rowBase + ty * 8 + 2 * i;
                int b0  = n0 >> 11, s0 = n0 & (SS - 1);
                int n1  = n0 + 1;
                int b1  = n1 >> 11, s1 = n1 & (SS - 1);
                dst[(((size_t)b0 * HH + h) * SS + s0) * DKK + dd] = lo;
                dst[(((size_t)b1 * HH + h) * SS + s1) * DKK + dd] = hi;
            }
        }
    } else {
        #pragma unroll
        for (int i = 0; i < 4; ++i) {
            int n0 = rowBase + ty * 8 + 2 * i;
            #pragma unroll
            for (int j = 0; j < 8; ++j) {
                float lo, hi;
                upk2(acc2[i][j], lo, hi);
                int col = colBase + tx * 8 + j;
                outp[(size_t)n0 * DD + col]       = lo;
                outp[(size_t)(n0 + 1) * DD + col] = hi;
            }
        }
    }
}

// ---------------------------------------------------------------------------
// Register-tiled causal flash attention.
// CTA = 128 threads, 64 queries. Key tiles of 64.
// Thread micro-tile: 4 queries x 8 keys (scores) / 4 queries x 8 dims (PV).
// qg = tid>>3 (0..15), kg = tid&7 (0..7; doubles as dim-group in PV).
// smem (dynamic 64KB): Qst[d][q], Kst[d][k], Vs[k][d], Pst[k][q].
// ---------------------------------------------------------------------------
__global__ __launch_bounds__(128)
void flash_kernel()
{
    extern __shared__ float sm[];
    float* Qst = sm;            // 64x64, d-major
    float* Kst = sm + 4096;     // 64x64, d-major
    float* Vsm = sm + 8192;     // 64x64, k-major
    float* Pst = sm + 12288;    // 64x64, k-major rows, q cols

    const int tid = threadIdx.x;
    const int qg  = tid >> 3;   // 0..15
    const int kg  = tid & 7;    // 0..7
    const int b   = blockIdx.z;
    const int h   = blockIdx.y;
    const int qb  = (gridDim.x - 1) - blockIdx.x;   // heavy blocks first

    const size_t headOff = (size_t)(b * HH + h) * SS * DKK;
    const float* Qh = g_q + headOff;
    const float* Kh = g_k + headOff;
    const float* Vh = g_v + headOff;

    // Stage Q (transposed, pre-scaled by 1/sqrt(dk)=0.125)
    #pragma unroll
    for (int it = 0; it < 8; ++it) {
        int idx = tid + it * 128;
        int r   = idx & 63;
        int c4  = (idx >> 6) << 2;
        float4 v = *(const float4*)(Qh + (size_t)(qb * 64 + r) * DKK + c4);
        Qst[(c4 + 0) * 64 + r] = v.x * 0.125f;
        Qst[(c4 + 1) * 64 + r] = v.y * 0.125f;
        Qst[(c4 + 2) * 64 + r] = v.z * 0.125f;
        Qst[(c4 + 3) * 64 + r] = v.w * 0.125f;
    }

    u64 O2[4][4];
    #pragma unroll
    for (int i = 0; i < 4; ++i)
        #pragma unroll
        for (int j = 0; j < 4; ++j) O2[i][j] = 0ull;
    float m[4] = {-1e30f, -1e30f, -1e30f, -1e30f};
    float l[4] = {0.f, 0.f, 0.f, 0.f};

    const uint32_t qAddr = smem_u32(Qst + qg * 4);
    const uint32_t kAddr = smem_u32(Kst + kg * 8);
    const uint32_t vAddr = smem_u32(Vsm + kg * 8);
    const uint32_t pAddr = smem_u32(Pst + qg * 4);

    const int ntiles = qb + 1;
    for (int t = 0; t < ntiles; ++t) {
        __syncthreads();   // protect smem from previous iteration's readers
        // K tile, transposed store (lanes span k -> conflict-free scatter)
        #pragma unroll
        for (int it = 0; it < 8; ++it) {
            int idx = tid + it * 128;
            int r   = idx & 63;
            int c4  = (idx >> 6) << 2;
            float4 v = *(const float4*)(Kh + (size_t)(t * 64 + r) * DKK + c4);
            Kst[(c4 + 0) * 64 + r] = v.x;
            Kst[(c4 + 1) * 64 + r] = v.y;
            Kst[(c4 + 2) * 64 + r] = v.z;
            Kst[(c4 + 3) * 64 + r] = v.w;
        }
        // V tile, natural copy
        #pragma unroll
        for (int it = 0; it < 8; ++it) {
            int idx = tid + it * 128;
            int r   = idx >> 4;
            int c4  = (idx & 15) << 2;
            *(float4*)&Vsm[r * 64 + c4] =
                *(const float4*)(Vh + (size_t)(t * 64 + r) * DKK + c4);
        }
        __syncthreads();

        // ---- scores: S[4q][8k] as f32x2 over k-pairs ----
        u64 S2[4][4];
        #pragma unroll
        for (int i = 0; i < 4; ++i)
            #pragma unroll
            for (int j = 0; j < 4; ++j) S2[i][j] = 0ull;

        #pragma unroll 4
        for (int d = 0; d < 64; ++d) {
            float4 aq = *(const float4*)(Qst + d * 64 + qg * 4);
            u64 aa[4];
            aa[0] = pk2(aq.x, aq.x); aa[1] = pk2(aq.y, aq.y);
            aa[2] = pk2(aq.z, aq.z); aa[3] = pk2(aq.w, aq.w);
            u64 kk[4];
            #pragma unroll
            for (int j = 0; j < 4; ++j)
                kk[j] = lds64(kAddr + (uint32_t)(d * 64) * 4u + (uint32_t)j * 8u);
            #pragma unroll
            for (int i = 0; i < 4; ++i)
                #pragma unroll
                for (int j = 0; j < 4; ++j)
                    ffma2(S2[i][j], aa[i], kk[j]);
        }

        // ---- softmax (online) ----
        float s[4][8];
        #pragma unroll
        for (int i = 0; i < 4; ++i)
            #pragma unroll
            for (int j = 0; j < 4; ++j)
                upk2(S2[i][j], s[i][2 * j], s[i][2 * j + 1]);

        if (t == ntiles - 1) {      // diagonal tile: causal mask
            #pragma unroll
            for (int i = 0; i < 4; ++i)
                #pragma unroll
                for (int j = 0; j < 8; ++j)
                    if (kg * 8 + j > qg * 4 + i) s[i][j] = -1e30f;
        }

        #pragma unroll
        for (int i = 0; i < 4; ++i) {
            float mn = s[i][0];
            #pragma unroll
            for (int j = 1; j < 8; ++j) mn = fmaxf(mn, s[i][j]);
            mn = fmaxf(mn, __shfl_xor_sync(0xffffffff, mn, 1));
            mn = fmaxf(mn, __shfl_xor_sync(0xffffffff, mn, 2));
            mn = fmaxf(mn, __shfl_xor_sync(0xffffffff, mn, 4));
            float mnew = fmaxf(m[i], mn);
            float corr = __expf(m[i] - mnew);
            m[i] = mnew;
            l[i] *= corr;
            u64 c2 = pk2(corr, corr);
            #pragma unroll
            for (int j = 0; j < 4; ++j) O2[i][j] = mul2(O2[i][j], c2);
            #pragma unroll
            for (int j = 0; j < 8; ++j) {
                float p = __expf(s[i][j] - mnew);
                l[i] += p;
                s[i][j] = p;
            }
        }

        // Store P transposed: Pst[k][q]
        #pragma unroll
        for (int j = 0; j < 8; ++j) {
            float4 pv = make_float4(s[0][j], s[1][j], s[2][j], s[3][j]);
            *(float4*)&Pst[(kg * 8 + j) * 64 + qg * 4] = pv;
        }
        __syncthreads();

        // ---- PV: O[4q][8d] += P[4q][64k] * V[64k][8d] ----
        #pragma unroll 4
        for (int k = 0; k < 64; ++k) {
            float4 pq = *(const float4*)((const char*)0 + 0, (const float4*)(Pst + k * 64 + qg * 4));
            u64 pp[4];
            pp[0] = pk2(pq.x, pq.x); pp[1] = pk2(pq.y, pq.y);
            pp[2] = pk2(pq.z, pq.z); pp[3] = pk2(pq.w, pq.w);
            u64 vv[4];
            #pragma unroll
            for (int j = 0; j < 4; ++j)
                vv[j] = lds64(vAddr + (uint32_t)(k * 64) * 4u + (uint32_t)j * 8u);
            #pragma unroll
            for (int i = 0; i < 4; ++i)
                #pragma unroll
                for (int j = 0; j < 4; ++j)
                    ffma2(O2[i][j], pp[i], vv[j]);
        }
    }

    // final l reduction across kg lanes + output
    #pragma unroll
    for (int i = 0; i < 4; ++i) {
        float li = l[i];
        li += __shfl_xor_sync(0xffffffff, li, 1);
        li += __shfl_xor_sync(0xffffffff, li, 2);
        li += __shfl_xor_sync(0xffffffff, li, 4);
        float inv = 1.0f / li;
        u64 inv2 = pk2(inv, inv);
        float o[8];
        #pragma unroll
        for (int j = 0; j < 4; ++j) {
            u64 r = mul2(O2[i][j], inv2);
            upk2(r, o[2 * j], o[2 * j + 1]);
        }
        float* dst = g_ctx + ((size_t)(b * SS + qb * 64 + qg * 4 + i)) * DD
                   + h * DKK + kg * 8;
        *(float4*)dst       = make_float4(o[0], o[1], o[2], o[3]);
        *(float4*)(dst + 4) = make_float4(o[4], o[5], o[6], o[7]);
    }
    (void)pAddr;
}

// ---------------------------------------------------------------------------
extern "C" void kernel_launch(void* const* d_in, const int* in_sizes, int n_in,
                              void* d_out, int out_size)
{
    (void)in_sizes; (void)n_in; (void)out_size;
    const float* Q  = (const float*)d_in[0];
    const float* K  = (const float*)d_in[1];
    const float* V  = (const float*)d_in[2];
    const float* Wq = (const float*)d_in[4];
    const float* Wk = (const float*)d_in[5];
    const float* Wv = (const float*)d_in[6];
    const float* Wo = (const float*)d_in[7];
    float* out = (float*)d_out;

    static bool attr_done = false;
    if (!attr_done) {
        cudaFuncSetAttribute(flash_kernel,
                             cudaFuncAttributeMaxDynamicSharedMemorySize,
                             64 * 1024);
        attr_done = true;
    }

    gemm_kernel<0><<<dim3(DD / 128, (BB * SS) / 128, 3), 256>>>(
        Q, K, V, Wq, Wk, Wv, nullptr);

    flash_kernel<<<dim3(SS / 64, HH, BB), 128, 64 * 1024>>>();

    gemm_kernel<1><<<dim3(DD / 128, (BB * SS) / 128, 1), 256>>>(
        nullptr, nullptr, nullptr, Wo, nullptr, nullptr, out);
}

// round 5
// speedup vs baseline: 4.7061x; 2.9700x over previous
#include <cuda_runtime.h>
#include <cuda_bf16.h>
#include <math.h>
#include <stdint.h>

#define BB   2
#define SS   2048
#define DD   768
#define HH   12
#define DKK  64

// Scratch (allocation-free)
__device__ float g_q[(size_t)BB * HH * SS * DKK];
__device__ float g_k[(size_t)BB * HH * SS * DKK];
__device__ float g_v[(size_t)BB * HH * SS * DKK];
__device__ float g_ctx[(size_t)BB * SS * DD];

// ------------------------------ helpers -------------------------------------
__device__ __forceinline__ uint32_t smem_u32(const void* p) {
    return (uint32_t)__cvta_generic_to_shared(p);
}
__device__ __forceinline__ uint32_t lds32(uint32_t a) {
    uint32_t v; asm volatile("ld.shared.b32 %0, [%1];" : "=r"(v) : "r"(a)); return v;
}
// D += A * B  (m16n8k16, bf16 in, f32 acc)
__device__ __forceinline__ void mma16816(float* c, const uint32_t* a,
                                         uint32_t b0, uint32_t b1) {
    asm volatile(
        "mma.sync.aligned.m16n8k16.row.col.f32.bf16.bf16.f32 "
        "{%0,%1,%2,%3}, {%4,%5,%6,%7}, {%8,%9}, {%0,%1,%2,%3};"
        : "+f"(c[0]), "+f"(c[1]), "+f"(c[2]), "+f"(c[3])
        : "r"(a[0]), "r"(a[1]), "r"(a[2]), "r"(a[3]), "r"(b0), "r"(b1));
}
__device__ __forceinline__ void ldmat4t(uint32_t* r, uint32_t addr) {
    asm volatile(
        "ldmatrix.sync.aligned.m8n8.x4.trans.shared.b16 {%0,%1,%2,%3}, [%4];"
        : "=r"(r[0]), "=r"(r[1]), "=r"(r[2]), "=r"(r[3]) : "r"(addr));
}
__device__ __forceinline__ uint32_t pkbf(float a, float b) {
    __nv_bfloat162 h = __floats2bfloat162_rn(a, b);
    return *(uint32_t*)&h;
}
// split pair (x,y) into packed bf16 hi and lo residual
__device__ __forceinline__ void split2(float x, float y, uint32_t &hi, uint32_t &lo) {
    float hx = __bfloat162float(__float2bfloat16(x));
    float hy = __bfloat162float(__float2bfloat16(y));
    hi = pkbf(x, y);
    lo = pkbf(x - hx, y - hy);
}

#define SA 144   // smem row stride in bytes (64 bf16 = 128B + 16 pad -> conflict-free)

// ---------------------------------------------------------------------------
// HMMA GEMM: C[4096,768] = X[4096,768] * W[768,768]^T, bf16 hi/lo 3-pass.
// CTA 256 thr (8 warps), tile 128x128, BK=64 (12 chunks).
// Warp grid 2(M)x4(N): each warp 64x32 -> 4x4 m16n8 acc tiles.
// smem: Ahi, Alo, Bhi, Blo each 128 rows x 144B = 18432B (total 73728B).
// ---------------------------------------------------------------------------
template<int MODE>
__global__ __launch_bounds__(256)
void gemm_tc(const float* __restrict__ x0, const float* __restrict__ x1,
             const float* __restrict__ x2, const float* __restrict__ w0,
             const float* __restrict__ w1, const float* __restrict__ w2,
             float* __restrict__ outp)
{
    extern __shared__ char sm[];
    char* Ahi = sm;
    char* Alo = sm + 18432;
    char* Bhi = sm + 36864;
    char* Blo = sm + 55296;
    const uint32_t uAhi = smem_u32(Ahi), uAlo = smem_u32(Alo);
    const uint32_t uBhi = smem_u32(Bhi), uBlo = smem_u32(Blo);

    const float* X;
    const float* W;
    if (MODE == 0) {
        X = (blockIdx.z == 0) ? x0 : (blockIdx.z == 1) ? x1 : x2;
        W = (blockIdx.z == 0) ? w0 : (blockIdx.z == 1) ? w1 : w2;
    } else {
        X = g_ctx;
        W = w0;
    }

    const int tid  = threadIdx.x;
    const int warp = tid >> 5;
    const int lane = tid & 31;
    const int g    = lane >> 2;      // group (row within tile)
    const int t    = lane & 3;       // thread-in-group (col pair)
    const int wm   = (warp >> 2) * 64;
    const int wn   = (warp & 3) * 32;
    const int rowBase = blockIdx.y * 128;
    const int colBase = blockIdx.x * 128;

    float acc[4][4][4];
    #pragma unroll
    for (int mi = 0; mi < 4; ++mi)
        #pragma unroll
        for (int ni = 0; ni < 4; ++ni)
            #pragma unroll
            for (int r = 0; r < 4; ++r) acc[mi][ni][r] = 0.f;

    for (int ch = 0; ch < 12; ++ch) {
        const int k0g = ch * 64;
        __syncthreads();   // previous compute done before overwriting smem
        #pragma unroll
        for (int it = 0; it < 8; ++it) {
            int idx = tid + it * 256;        // 0..2047
            int r   = idx >> 4;              // 0..127
            int c4  = (idx & 15) * 4;        // 0..60
            {
                float4 v = *(const float4*)(X + (size_t)(rowBase + r) * DD + k0g + c4);
                uint32_t h0, l0, h1, l1;
                split2(v.x, v.y, h0, l0);
                split2(v.z, v.w, h1, l1);
                *(uint2*)(Ahi + r * SA + c4 * 2) = make_uint2(h0, h1);
                *(uint2*)(Alo + r * SA + c4 * 2) = make_uint2(l0, l1);
            }
            {
                float4 v = *(const float4*)(W + (size_t)(colBase + r) * DD + k0g + c4);
                uint32_t h0, l0, h1, l1;
                split2(v.x, v.y, h0, l0);
                split2(v.z, v.w, h1, l1);
                *(uint2*)(Bhi + r * SA + c4 * 2) = make_uint2(h0, h1);
                *(uint2*)(Blo + r * SA + c4 * 2) = make_uint2(l0, l1);
            }
        }
        __syncthreads();

        #pragma unroll
        for (int kt = 0; kt < 4; ++kt) {
            const uint32_t koff = (uint32_t)(kt * 16 + 2 * t) * 2u;
            uint32_t afh[4][4], afl[4][4];
            #pragma unroll
            for (int mi = 0; mi < 4; ++mi) {
                uint32_t ro = (uint32_t)(wm + mi * 16 + g) * SA + koff;
                afh[mi][0] = lds32(uAhi + ro);
                afh[mi][1] = lds32(uAhi + ro + 8 * SA);
                afh[mi][2] = lds32(uAhi + ro + 16);
                afh[mi][3] = lds32(uAhi + ro + 8 * SA + 16);
                afl[mi][0] = lds32(uAlo + ro);
                afl[mi][1] = lds32(uAlo + ro + 8 * SA);
                afl[mi][2] = lds32(uAlo + ro + 16);
                afl[mi][3] = lds32(uAlo + ro + 8 * SA + 16);
            }
            #pragma unroll
            for (int ni = 0; ni < 4; ++ni) {
                uint32_t co = (uint32_t)(wn + ni * 8 + g) * SA + koff;
                uint32_t b0 = lds32(uBhi + co), b1 = lds32(uBhi + co + 16);
                #pragma unroll
                for (int mi = 0; mi < 4; ++mi) {
                    mma16816(acc[mi][ni], afh[mi], b0, b1);
                    mma16816(acc[mi][ni], afl[mi], b0, b1);
                }
                uint32_t c0 = lds32(uBlo + co), c1 = lds32(uBlo + co + 16);
                #pragma unroll
                for (int mi = 0; mi < 4; ++mi)
                    mma16816(acc[mi][ni], afh[mi], c0, c1);
            }
        }
    }

    // epilogue
    #pragma unroll
    for (int mi = 0; mi < 4; ++mi) {
        int r0 = rowBase + wm + mi * 16 + g;
        int r1 = r0 + 8;
        #pragma unroll
        for (int ni = 0; ni < 4; ++ni) {
            int col = colBase + wn + ni * 8 + 2 * t;
            if (MODE == 0) {
                float* dst = (blockIdx.z == 0) ? g_q : (blockIdx.z == 1) ? g_k : g_v;
                int h = col >> 6, dk = col & 63;
                int b0 = r0 >> 11, s0 = r0 & (SS - 1);
                int b1 = r1 >> 11, s1 = r1 & (SS - 1);
                *(float2*)(dst + (((size_t)b0 * HH + h) * SS + s0) * DKK + dk) =
                    make_float2(acc[mi][ni][0], acc[mi][ni][1]);
                *(float2*)(dst + (((size_t)b1 * HH + h) * SS + s1) * DKK + dk) =
                    make_float2(acc[mi][ni][2], acc[mi][ni][3]);
            } else {
                *(float2*)(outp + (size_t)r0 * DD + col) =
                    make_float2(acc[mi][ni][0], acc[mi][ni][1]);
                *(float2*)(outp + (size_t)r1 * DD + col) =
                    make_float2(acc[mi][ni][2], acc[mi][ni][3]);
            }
        }
    }
}

// ---------------------------------------------------------------------------
// HMMA causal flash attention, FA2 style, hi/lo 3-pass.
// CTA 128 thr (4 warps), 64 queries; each warp owns 16 q rows.
// Key tiles of 64.  S = Q K^T via mma (lds.b32 frags, both k-contiguous);
// P reused from acc regs as A-fragments; V via ldmatrix.x4.trans.
// smem: Qhi,Qlo,Khi,Klo,Vhi,Vlo each 64 x 144B = 9216B (total 55296B).
// ---------------------------------------------------------------------------
__global__ __launch_bounds__(128)
void flash_tc()
{
    extern __shared__ char fsm[];
    const uint32_t uQhi = smem_u32(fsm);
    const uint32_t uQlo = uQhi + 9216;
    const uint32_t uKhi = uQhi + 18432;
    const uint32_t uKlo = uQhi + 27648;
    const uint32_t uVhi = uQhi + 36864;
    const uint32_t uVlo = uQhi + 46080;
    char* Qhi = fsm;          char* Qlo = fsm + 9216;
    char* Khi = fsm + 18432;  char* Klo = fsm + 27648;
    char* Vhi = fsm + 36864;  char* Vlo = fsm + 46080;

    const int tid  = threadIdx.x;
    const int warp = tid >> 5;
    const int lane = tid & 31;
    const int g    = lane >> 2;
    const int t    = lane & 3;
    const int b    = blockIdx.z;
    const int h    = blockIdx.y;
    const int qb   = (gridDim.x - 1) - blockIdx.x;   // heavy blocks first

    const size_t headOff = (size_t)(b * HH + h) * SS * DKK;
    const float* Qg = g_q + headOff;
    const float* Kg = g_k + headOff;
    const float* Vg = g_v + headOff;

    // stage Q once (scaled by 1/8), split hi/lo — FULL 64x64 tile (it<8!)
    #pragma unroll
    for (int it = 0; it < 8; ++it) {
        int idx = tid + it * 128;        // 0..1023
        int r   = idx >> 4;              // 0..63
        int c4  = (idx & 15) * 4;        // 0..60
        float4 v = *(const float4*)(Qg + (size_t)(qb * 64 + r) * DKK + c4);
        uint32_t h0, l0, h1, l1;
        split2(v.x * 0.125f, v.y * 0.125f, h0, l0);
        split2(v.z * 0.125f, v.w * 0.125f, h1, l1);
        *(uint2*)(Qhi + r * SA + c4 * 2) = make_uint2(h0, h1);
        *(uint2*)(Qlo + r * SA + c4 * 2) = make_uint2(l0, l1);
    }

    float accO[8][4];
    #pragma unroll
    for (int d = 0; d < 8; ++d)
        #pragma unroll
        for (int r = 0; r < 4; ++r) accO[d][r] = 0.f;
    float m0 = -1e30f, m1 = -1e30f, l0 = 0.f, l1 = 0.f;

    const int qrow = warp * 16 + g;   // local q row (and +8)

    for (int kt_tile = 0; kt_tile <= qb; ++kt_tile) {
        __syncthreads();
        #pragma unroll
        for (int it = 0; it < 8; ++it) {
            int idx = tid + it * 128;    // 0..1023 — FULL tile
            int r   = idx >> 4;          // 0..63
            int c4  = (idx & 15) * 4;
            {
                float4 v = *(const float4*)(Kg + (size_t)(kt_tile * 64 + r) * DKK + c4);
                uint32_t h0, lo0, h1, lo1;
                split2(v.x, v.y, h0, lo0);
                split2(v.z, v.w, h1, lo1);
                *(uint2*)(Khi + r * SA + c4 * 2) = make_uint2(h0, h1);
                *(uint2*)(Klo + r * SA + c4 * 2) = make_uint2(lo0, lo1);
            }
            {
                float4 v = *(const float4*)(Vg + (size_t)(kt_tile * 64 + r) * DKK + c4);
                uint32_t h0, lo0, h1, lo1;
                split2(v.x, v.y, h0, lo0);
                split2(v.z, v.w, h1, lo1);
                *(uint2*)(Vhi + r * SA + c4 * 2) = make_uint2(h0, h1);
                *(uint2*)(Vlo + r * SA + c4 * 2) = make_uint2(lo0, lo1);
            }
        }
        __syncthreads();

        // ---- S = Q K^T : 8 n-tiles of 8 keys ----
        float sacc[8][4];
        #pragma unroll
        for (int nt = 0; nt < 8; ++nt)
            #pragma unroll
            for (int r = 0; r < 4; ++r) sacc[nt][r] = 0.f;

        #pragma unroll
        for (int kt = 0; kt < 4; ++kt) {
            const uint32_t koff = (uint32_t)(kt * 16 + 2 * t) * 2u;
            uint32_t qa[4], ql[4];
            uint32_t ro = (uint32_t)qrow * SA + koff;
            qa[0] = lds32(uQhi + ro);          qa[1] = lds32(uQhi + ro + 8 * SA);
            qa[2] = lds32(uQhi + ro + 16);     qa[3] = lds32(uQhi + ro + 8 * SA + 16);
            ql[0] = lds32(uQlo + ro);          ql[1] = lds32(uQlo + ro + 8 * SA);
            ql[2] = lds32(uQlo + ro + 16);     ql[3] = lds32(uQlo + ro + 8 * SA + 16);
            #pragma unroll
            for (int nt = 0; nt < 8; ++nt) {
                uint32_t co = (uint32_t)(nt * 8 + g) * SA + koff;
                uint32_t b0 = lds32(uKhi + co), b1 = lds32(uKhi + co + 16);
                mma16816(sacc[nt], qa, b0, b1);
                mma16816(sacc[nt], ql, b0, b1);
                uint32_t c0 = lds32(uKlo + co), c1 = lds32(uKlo + co + 16);
                mma16816(sacc[nt], qa, c0, c1);
            }
        }

        // ---- causal mask on diagonal tile ----
        if (kt_tile == qb) {
            #pragma unroll
            for (int nt = 0; nt < 8; ++nt) {
                int kc = nt * 8 + 2 * t;
                if (kc     > qrow)     sacc[nt][0] = -1e30f;
                if (kc + 1 > qrow)     sacc[nt][1] = -1e30f;
                if (kc     > qrow + 8) sacc[nt][2] = -1e30f;
                if (kc + 1 > qrow + 8) sacc[nt][3] = -1e30f;
            }
        }

        // ---- online softmax ----
        float mx0 = -1e30f, mx1 = -1e30f;
        #pragma unroll
        for (int nt = 0; nt < 8; ++nt) {
            mx0 = fmaxf(mx0, fmaxf(sacc[nt][0], sacc[nt][1]));
            mx1 = fmaxf(mx1, fmaxf(sacc[nt][2], sacc[nt][3]));
        }
        mx0 = fmaxf(mx0, __shfl_xor_sync(0xffffffff, mx0, 1));
        mx0 = fmaxf(mx0, __shfl_xor_sync(0xffffffff, mx0, 2));
        mx1 = fmaxf(mx1, __shfl_xor_sync(0xffffffff, mx1, 1));
        mx1 = fmaxf(mx1, __shfl_xor_sync(0xffffffff, mx1, 2));
        float mn0 = fmaxf(m0, mx0), mn1 = fmaxf(m1, mx1);
        float cr0 = __expf(m0 - mn0), cr1 = __expf(m1 - mn1);
        m0 = mn0; m1 = mn1;
        l0 *= cr0; l1 *= cr1;
        #pragma unroll
        for (int d = 0; d < 8; ++d) {
            accO[d][0] *= cr0; accO[d][1] *= cr0;
            accO[d][2] *= cr1; accO[d][3] *= cr1;
        }

        // ---- P = exp(S - m), build A-fragments (hi/lo) ----
        uint32_t pah[4][4], pal[4][4];
        #pragma unroll
        for (int nt = 0; nt < 8; ++nt) {
            float p0 = __expf(sacc[nt][0] - mn0);
            float p1 = __expf(sacc[nt][1] - mn0);
            float p2 = __expf(sacc[nt][2] - mn1);
            float p3 = __expf(sacc[nt][3] - mn1);
            l0 += p0 + p1;
            l1 += p2 + p3;
            uint32_t h01, l01, h23, l23;
            split2(p0, p1, h01, l01);
            split2(p2, p3, h23, l23);
            int kt = nt >> 1;
            if ((nt & 1) == 0) {
                pah[kt][0] = h01; pah[kt][1] = h23;
                pal[kt][0] = l01; pal[kt][1] = l23;
            } else {
                pah[kt][2] = h01; pah[kt][3] = h23;
                pal[kt][2] = l01; pal[kt][3] = l23;
            }
        }

        // ---- O += P V ----
        const int mat = lane >> 3;
        const int rr  = lane & 7;
        #pragma unroll
        for (int kt = 0; kt < 4; ++kt) {
            #pragma unroll
            for (int pr = 0; pr < 4; ++pr) {   // d-tile pairs
                uint32_t off = (uint32_t)(kt * 16 + rr + (mat & 1) * 8) * SA
                             + (uint32_t)(pr * 16 + (mat >> 1) * 8) * 2u;
                uint32_t vh[4], vl[4];
                ldmat4t(vh, uVhi + off);
                mma16816(accO[2 * pr],     pah[kt], vh[0], vh[1]);
                mma16816(accO[2 * pr],     pal[kt], vh[0], vh[1]);
                mma16816(accO[2 * pr + 1], pah[kt], vh[2], vh[3]);
                mma16816(accO[2 * pr + 1], pal[kt], vh[2], vh[3]);
                ldmat4t(vl, uVlo + off);
                mma16816(accO[2 * pr],     pah[kt], vl[0], vl[1]);
                mma16816(accO[2 * pr + 1], pah[kt], vl[2], vl[3]);
            }
        }
    }

    // ---- finalize ----
    l0 += __shfl_xor_sync(0xffffffff, l0, 1);
    l0 += __shfl_xor_sync(0xffffffff, l0, 2);
    l1 += __shfl_xor_sync(0xffffffff, l1, 1);
    l1 += __shfl_xor_sync(0xffffffff, l1, 2);
    float inv0 = 1.0f / l0, inv1 = 1.0f / l1;

    int q0 = qb * 64 + qrow;
    float* dst0 = g_ctx + ((size_t)b * SS + q0) * DD + h * DKK;
    float* dst1 = dst0 + 8 * DD;
    #pragma unroll
    for (int d = 0; d < 8; ++d) {
        int col = d * 8 + 2 * t;
        *(float2*)(dst0 + col) = make_float2(accO[d][0] * inv0, accO[d][1] * inv0);
        *(float2*)(dst1 + col) = make_float2(accO[d][2] * inv1, accO[d][3] * inv1);
    }
}

// ---------------------------------------------------------------------------
extern "C" void kernel_launch(void* const* d_in, const int* in_sizes, int n_in,
                              void* d_out, int out_size)
{
    (void)in_sizes; (void)n_in; (void)out_size;
    const float* Q  = (const float*)d_in[0];
    const float* K  = (const float*)d_in[1];
    const float* V  = (const float*)d_in[2];
    const float* Wq = (const float*)d_in[4];
    const float* Wk = (const float*)d_in[5];
    const float* Wv = (const float*)d_in[6];
    const float* Wo = (const float*)d_in[7];
    float* out = (float*)d_out;

    constexpr int GEMM_SMEM  = 4 * 18432;   // 73728
    constexpr int FLASH_SMEM = 6 * 9216;    // 55296
    static bool attr_done = false;
    if (!attr_done) {
        cudaFuncSetAttribute(gemm_tc<0>,
                             cudaFuncAttributeMaxDynamicSharedMemorySize, GEMM_SMEM);
        cudaFuncSetAttribute(gemm_tc<1>,
                             cudaFuncAttributeMaxDynamicSharedMemorySize, GEMM_SMEM);
        cudaFuncSetAttribute(flash_tc,
                             cudaFuncAttributeMaxDynamicSharedMemorySize, FLASH_SMEM);
        attr_done = true;
    }

    gemm_tc<0><<<dim3(DD / 128, (BB * SS) / 128, 3), 256, GEMM_SMEM>>>(
        Q, K, V, Wq, Wk, Wv, nullptr);

    flash_tc<<<dim3(SS / 64, HH, BB), 128, FLASH_SMEM>>>();

    gemm_tc<1><<<dim3(DD / 128, (BB * SS) / 128, 1), 256, GEMM_SMEM>>>(
        nullptr, nullptr, nullptr, Wo, nullptr, nullptr, out);
}

// round 6
// speedup vs baseline: 5.3613x; 1.1392x over previous
#include <cuda_runtime.h>
#include <cuda_bf16.h>
#include <math.h>
#include <stdint.h>

#define BB   2
#define SS   2048
#define DD   768
#define HH   12
#define DKK  64

#define XN 3145728   // 4096*768
#define WN 589824    // 768*768
#define HN 3145728   // BB*HH*SS*DKK
#define CN 3145728   // BB*SS*DD

// bf16 hi/lo scratch (allocation-free), 16B-aligned for cp.async / vector ops
__device__ __align__(128) __nv_bfloat16 g_xhi[3 * XN];
__device__ __align__(128) __nv_bfloat16 g_xlo[3 * XN];
__device__ __align__(128) __nv_bfloat16 g_whi[4 * WN];
__device__ __align__(128) __nv_bfloat16 g_wlo[4 * WN];
__device__ __align__(128) __nv_bfloat16 g_qhi[HN];
__device__ __align__(128) __nv_bfloat16 g_qlo[HN];
__device__ __align__(128) __nv_bfloat16 g_khi[HN];
__device__ __align__(128) __nv_bfloat16 g_klo[HN];
__device__ __align__(128) __nv_bfloat16 g_vhi[HN];
__device__ __align__(128) __nv_bfloat16 g_vlo[HN];
__device__ __align__(128) __nv_bfloat16 g_chi[CN];
__device__ __align__(128) __nv_bfloat16 g_clo[CN];

// ------------------------------ helpers -------------------------------------
__device__ __forceinline__ uint32_t smem_u32(const void* p) {
    return (uint32_t)__cvta_generic_to_shared(p);
}
__device__ __forceinline__ void mma16816(float* c, const uint32_t* a,
                                         uint32_t b0, uint32_t b1) {
    asm volatile(
        "mma.sync.aligned.m16n8k16.row.col.f32.bf16.bf16.f32 "
        "{%0,%1,%2,%3}, {%4,%5,%6,%7}, {%8,%9}, {%0,%1,%2,%3};"
        : "+f"(c[0]), "+f"(c[1]), "+f"(c[2]), "+f"(c[3])
        : "r"(a[0]), "r"(a[1]), "r"(a[2]), "r"(a[3]), "r"(b0), "r"(b1));
}
__device__ __forceinline__ void ldmat4(uint32_t* r, uint32_t addr) {
    asm volatile(
        "ldmatrix.sync.aligned.m8n8.x4.shared.b16 {%0,%1,%2,%3}, [%4];"
        : "=r"(r[0]), "=r"(r[1]), "=r"(r[2]), "=r"(r[3]) : "r"(addr));
}
__device__ __forceinline__ void ldmat4t(uint32_t* r, uint32_t addr) {
    asm volatile(
        "ldmatrix.sync.aligned.m8n8.x4.trans.shared.b16 {%0,%1,%2,%3}, [%4];"
        : "=r"(r[0]), "=r"(r[1]), "=r"(r[2]), "=r"(r[3]) : "r"(addr));
}
__device__ __forceinline__ uint32_t pkbf(float a, float b) {
    __nv_bfloat162 h = __floats2bfloat162_rn(a, b);
    return *(uint32_t*)&h;
}
__device__ __forceinline__ void split2(float x, float y, uint32_t &hi, uint32_t &lo) {
    float hx = __bfloat162float(__float2bfloat16(x));
    float hy = __bfloat162float(__float2bfloat16(y));
    hi = pkbf(x, y);
    lo = pkbf(x - hx, y - hy);
}
__device__ __forceinline__ void cp16(uint32_t dst, const void* src) {
    asm volatile("cp.async.cg.shared.global [%0], [%1], 16;"
                 :: "r"(dst), "l"(src));
}
__device__ __forceinline__ void cpcommit() {
    asm volatile("cp.async.commit_group;" ::: "memory");
}
template<int N>
__device__ __forceinline__ void cpwait() {
    asm volatile("cp.async.wait_group %0;" :: "n"(N) : "memory");
}

#define SA 144   // smem row stride bytes (64 bf16 = 128B data + 16B pad)

// ---------------------------------------------------------------------------
// Convert kernels: fp32 -> bf16 hi + lo residual (one pass, global scratch)
// ---------------------------------------------------------------------------
__global__ __launch_bounds__(256)
void conv_x(const float* __restrict__ x0, const float* __restrict__ x1,
            const float* __restrict__ x2)
{
    const float* src = (blockIdx.z == 0) ? x0 : (blockIdx.z == 1) ? x1 : x2;
    size_t off = (size_t)blockIdx.z * XN;
    size_t i4  = ((size_t)blockIdx.x * 256 + threadIdx.x) * 4;
    float4 v = *(const float4*)(src + i4);
    uint32_t h0, l0, h1, l1;
    split2(v.x, v.y, h0, l0);
    split2(v.z, v.w, h1, l1);
    *(uint2*)(g_xhi + off + i4) = make_uint2(h0, h1);
    *(uint2*)(g_xlo + off + i4) = make_uint2(l0, l1);
}

__global__ __launch_bounds__(256)
void conv_w(const float* __restrict__ w0, const float* __restrict__ w1,
            const float* __restrict__ w2, const float* __restrict__ w3)
{
    const float* src = (blockIdx.z == 0) ? w0 : (blockIdx.z == 1) ? w1
                     : (blockIdx.z == 2) ? w2 : w3;
    size_t off = (size_t)blockIdx.z * WN;
    size_t i4  = ((size_t)blockIdx.x * 256 + threadIdx.x) * 4;
    float4 v = *(const float4*)(src + i4);
    uint32_t h0, l0, h1, l1;
    split2(v.x, v.y, h0, l0);
    split2(v.z, v.w, h1, l1);
    *(uint2*)(g_whi + off + i4) = make_uint2(h0, h1);
    *(uint2*)(g_wlo + off + i4) = make_uint2(l0, l1);
}

// ---------------------------------------------------------------------------
// Pipelined HMMA GEMM: C[4096,768] = A[4096,768] * W[768,768]^T
// Operands preconverted bf16 hi/lo. 256 thr, tile 128x128, BK=64 (12 chunks),
// cp.async double-buffered, ldmatrix fragment feeds, hi/lo 3-pass MMA.
// MODE 0: A=g_x(z), B=g_w(z); epilogue -> bf16 hi/lo head-split q/k/v
//         (q scaled 0.125). MODE 1: A=g_c, B=g_w(3); epilogue fp32 out.
// smem: 2 buffers x 4 arrays x (128 rows x 144B) = 147456B.
// ---------------------------------------------------------------------------
#define GBUF 73728

template<int MODE>
__global__ __launch_bounds__(256)
void gemm_bf(float* __restrict__ outp)
{
    extern __shared__ char sm[];
    const uint32_t base = smem_u32(sm);

    const int tid  = threadIdx.x;
    const int warp = tid >> 5;
    const int lane = tid & 31;
    const int g    = lane >> 2;
    const int t    = lane & 3;
    const int wm   = (warp >> 2) * 64;
    const int wn   = (warp & 3) * 32;
    const int rowBase = blockIdx.y * 128;
    const int colBase = blockIdx.x * 128;
    const int z = blockIdx.z;

    const __nv_bfloat16 *Ahi, *Alo, *Bhi, *Blo;
    if (MODE == 0) {
        Ahi = g_xhi + (size_t)z * XN; Alo = g_xlo + (size_t)z * XN;
        Bhi = g_whi + (size_t)z * WN; Blo = g_wlo + (size_t)z * WN;
    } else {
        Ahi = g_chi; Alo = g_clo;
        Bhi = g_whi + (size_t)3 * WN; Blo = g_wlo + (size_t)3 * WN;
    }

    // ldmatrix per-lane address offsets
    const uint32_t laneA = (uint32_t)(((lane & 7) + ((lane >> 3) & 1) * 8) * SA
                                      + (lane >> 4) * 16);
    const uint32_t laneB = (uint32_t)(((lane & 7) + ((lane >> 4) & 1) * 8) * SA
                                      + ((lane >> 3) & 1) * 16);

    float acc[4][4][4];
    #pragma unroll
    for (int mi = 0; mi < 4; ++mi)
        #pragma unroll
        for (int ni = 0; ni < 4; ++ni)
            #pragma unroll
            for (int r = 0; r < 4; ++r) acc[mi][ni][r] = 0.f;

    // chunk loader: 4 arrays x 128 rows x 8 x 16B, 16 cp per thread
    auto load_chunk = [&](int ch, int p) {
        const int k0 = ch * 64;
        uint32_t sb = base + p * GBUF;
        #pragma unroll
        for (int it = 0; it < 4; ++it) {
            int idx = tid + it * 256;        // 0..1023
            int r   = idx >> 3;              // 0..127
            int sg  = idx & 7;               // 16B segment
            uint32_t d = (uint32_t)(r * SA + sg * 16);
            cp16(sb +             d, Ahi + (size_t)(rowBase + r) * DD + k0 + sg * 8);
            cp16(sb + 18432u +    d, Alo + (size_t)(rowBase + r) * DD + k0 + sg * 8);
            cp16(sb + 36864u +    d, Bhi + (size_t)(colBase + r) * DD + k0 + sg * 8);
            cp16(sb + 55296u +    d, Blo + (size_t)(colBase + r) * DD + k0 + sg * 8);
        }
    };

    load_chunk(0, 0);
    cpcommit();

    for (int ch = 0; ch < 12; ++ch) {
        if (ch < 11) { load_chunk(ch + 1, (ch + 1) & 1); cpcommit(); cpwait<1>(); }
        else         { cpwait<0>(); }
        __syncthreads();

        const uint32_t uAh = base + (ch & 1) * GBUF;
        const uint32_t uAl = uAh + 18432u;
        const uint32_t uBh = uAh + 36864u;
        const uint32_t uBl = uAh + 55296u;

        #pragma unroll
        for (int kt = 0; kt < 4; ++kt) {
            const uint32_t ko = (uint32_t)kt * 32u;
            uint32_t afh[4][4], afl[4][4];
            #pragma unroll
            for (int mi = 0; mi < 4; ++mi) {
                uint32_t ao = (uint32_t)((wm + mi * 16) * SA) + ko;
                ldmat4(afh[mi], uAh + ao + laneA);
                ldmat4(afl[mi], uAl + ao + laneA);
            }
            uint32_t bh[2][4], bl[2][4];
            #pragma unroll
            for (int np = 0; np < 2; ++np) {
                uint32_t bo = (uint32_t)((wn + np * 16) * SA) + ko;
                ldmat4(bh[np], uBh + bo + laneB);
                ldmat4(bl[np], uBl + bo + laneB);
            }
            #pragma unroll
            for (int ni = 0; ni < 4; ++ni) {
                uint32_t b0h = bh[ni >> 1][(ni & 1) * 2];
                uint32_t b1h = bh[ni >> 1][(ni & 1) * 2 + 1];
                uint32_t b0l = bl[ni >> 1][(ni & 1) * 2];
                uint32_t b1l = bl[ni >> 1][(ni & 1) * 2 + 1];
                #pragma unroll
                for (int mi = 0; mi < 4; ++mi) {
                    mma16816(acc[mi][ni], afh[mi], b0h, b1h);
                    mma16816(acc[mi][ni], afl[mi], b0h, b1h);
                    mma16816(acc[mi][ni], afh[mi], b0l, b1l);
                }
            }
        }
        __syncthreads();
    }

    // epilogue
    const float sc = (MODE == 0 && z == 0) ? 0.125f : 1.0f;
    #pragma unroll
    for (int mi = 0; mi < 4; ++mi) {
        int r0 = rowBase + wm + mi * 16 + g;
        int r1 = r0 + 8;
        #pragma unroll
        for (int ni = 0; ni < 4; ++ni) {
            int col = colBase + wn + ni * 8 + 2 * t;
            if (MODE == 0) {
                __nv_bfloat16* dhi = (z == 0) ? g_qhi : (z == 1) ? g_khi : g_vhi;
                __nv_bfloat16* dlo = (z == 0) ? g_qlo : (z == 1) ? g_klo : g_vlo;
                int h = col >> 6, dk = col & 63;
                int b0 = r0 >> 11, s0 = r0 & (SS - 1);
                int b1 = r1 >> 11, s1 = r1 & (SS - 1);
                size_t i0 = (((size_t)b0 * HH + h) * SS + s0) * DKK + dk;
                size_t i1 = (((size_t)b1 * HH + h) * SS + s1) * DKK + dk;
                uint32_t hi, lo;
                split2(acc[mi][ni][0] * sc, acc[mi][ni][1] * sc, hi, lo);
                *(uint32_t*)(dhi + i0) = hi;
                *(uint32_t*)(dlo + i0) = lo;
                split2(acc[mi][ni][2] * sc, acc[mi][ni][3] * sc, hi, lo);
                *(uint32_t*)(dhi + i1) = hi;
                *(uint32_t*)(dlo + i1) = lo;
            } else {
                *(float2*)(outp + (size_t)r0 * DD + col) =
                    make_float2(acc[mi][ni][0], acc[mi][ni][1]);
                *(float2*)(outp + (size_t)r1 * DD + col) =
                    make_float2(acc[mi][ni][2], acc[mi][ni][3]);
            }
        }
    }
}

// ---------------------------------------------------------------------------
// Pipelined HMMA causal flash attention. 128 thr (4 warps), 64 q per CTA,
// 64-key tiles, cp.async double-buffered K/V, ldmatrix feeds, hi/lo 3-pass.
// Inputs: preconverted bf16 hi/lo q (scaled) / k / v.  Output: bf16 hi/lo ctx.
// smem: Q hi/lo 2x9216 + 2 buffers x (Khi,Klo,Vhi,Vlo x 9216) = 92160B.
// ---------------------------------------------------------------------------
#define FBUF 36864
#define FQ   18432

__global__ __launch_bounds__(128)
void flash_tc()
{
    extern __shared__ char fsm[];
    const uint32_t base = smem_u32(fsm);
    const uint32_t uQh = base, uQl = base + 9216u;

    const int tid  = threadIdx.x;
    const int warp = tid >> 5;
    const int lane = tid & 31;
    const int g    = lane >> 2;
    const int t    = lane & 3;
    const int b    = blockIdx.z;
    const int h    = blockIdx.y;
    const int qb   = (gridDim.x - 1) - blockIdx.x;   // heavy blocks first

    const size_t headOff = (size_t)(b * HH + h) * SS * DKK;

    const uint32_t laneA = (uint32_t)(((lane & 7) + ((lane >> 3) & 1) * 8) * SA
                                      + (lane >> 4) * 16);
    const uint32_t laneB = (uint32_t)(((lane & 7) + ((lane >> 4) & 1) * 8) * SA
                                      + ((lane >> 3) & 1) * 16);

    // K/V tile loader: 4 arrays x 64 rows x 8 seg, 16 cp per thread
    auto load_kv = [&](int kt_tile, int p) {
        uint32_t sb = base + FQ + p * FBUF;
        #pragma unroll
        for (int it = 0; it < 4; ++it) {
            int idx = tid + it * 128;        // 0..511
            int r   = idx >> 3;              // 0..63
            int sg  = idx & 7;
            size_t  s = headOff + (size_t)(kt_tile * 64 + r) * DKK + sg * 8;
            uint32_t d = (uint32_t)(r * SA + sg * 16);
            cp16(sb +          d, g_khi + s);
            cp16(sb + 9216u  + d, g_klo + s);
            cp16(sb + 18432u + d, g_vhi + s);
            cp16(sb + 27648u + d, g_vlo + s);
        }
    };

    // stage Q hi/lo (2 arrays x 64 rows x 8 seg, 8 cp per thread)
    #pragma unroll
    for (int it = 0; it < 4; ++it) {
        int idx = tid + it * 128;
        int r   = idx >> 3;
        int sg  = idx & 7;
        size_t  s = headOff + (size_t)(qb * 64 + r) * DKK + sg * 8;
        uint32_t d = (uint32_t)(r * SA + sg * 16);
        cp16(uQh + d, g_qhi + s);
        cp16(uQl + d, g_qlo + s);
    }
    load_kv(0, 0);
    cpcommit();

    float accO[8][4];
    #pragma unroll
    for (int d = 0; d < 8; ++d)
        #pragma unroll
        for (int r = 0; r < 4; ++r) accO[d][r] = 0.f;
    float m0 = -1e30f, m1 = -1e30f, l0 = 0.f, l1 = 0.f;

    const int qrow = warp * 16 + g;
    const int ntl  = qb + 1;

    for (int ch = 0; ch < ntl; ++ch) {
        if (ch < ntl - 1) { load_kv(ch + 1, (ch + 1) & 1); cpcommit(); cpwait<1>(); }
        else              { cpwait<0>(); }
        __syncthreads();

        const uint32_t uKh = base + FQ + (ch & 1) * FBUF;
        const uint32_t uKl = uKh + 9216u;
        const uint32_t uVh = uKh + 18432u;
        const uint32_t uVl = uKh + 27648u;

        // ---- S = Q K^T ----
        float sacc[8][4];
        #pragma unroll
        for (int nt = 0; nt < 8; ++nt)
            #pragma unroll
            for (int r = 0; r < 4; ++r) sacc[nt][r] = 0.f;

        #pragma unroll
        for (int kt = 0; kt < 4; ++kt) {
            const uint32_t ko = (uint32_t)kt * 32u;
            uint32_t qh[4], ql[4];
            uint32_t ao = (uint32_t)(warp * 16 * SA) + ko;
            ldmat4(qh, uQh + ao + laneA);
            ldmat4(ql, uQl + ao + laneA);
            uint32_t kh[4][4], kl[4][4];
            #pragma unroll
            for (int np = 0; np < 4; ++np) {
                uint32_t bo = (uint32_t)(np * 16 * SA) + ko;
                ldmat4(kh[np], uKh + bo + laneB);
                ldmat4(kl[np], uKl + bo + laneB);
            }
            #pragma unroll
            for (int nt = 0; nt < 8; ++nt) {
                uint32_t b0h = kh[nt >> 1][(nt & 1) * 2];
                uint32_t b1h = kh[nt >> 1][(nt & 1) * 2 + 1];
                uint32_t b0l = kl[nt >> 1][(nt & 1) * 2];
                uint32_t b1l = kl[nt >> 1][(nt & 1) * 2 + 1];
                mma16816(sacc[nt], qh, b0h, b1h);
                mma16816(sacc[nt], ql, b0h, b1h);
                mma16816(sacc[nt], qh, b0l, b1l);
            }
        }

        // ---- causal mask on diagonal tile ----
        if (ch == qb) {
            #pragma unroll
            for (int nt = 0; nt < 8; ++nt) {
                int kc = nt * 8 + 2 * t;
                if (kc     > qrow)     sacc[nt][0] = -1e30f;
                if (kc + 1 > qrow)     sacc[nt][1] = -1e30f;
                if (kc     > qrow + 8) sacc[nt][2] = -1e30f;
                if (kc + 1 > qrow + 8) sacc[nt][3] = -1e30f;
            }
        }

        // ---- online softmax ----
        float mx0 = -1e30f, mx1 = -1e30f;
        #pragma unroll
        for (int nt = 0; nt < 8; ++nt) {
            mx0 = fmaxf(mx0, fmaxf(sacc[nt][0], sacc[nt][1]));
            mx1 = fmaxf(mx1, fmaxf(sacc[nt][2], sacc[nt][3]));
        }
        mx0 = fmaxf(mx0, __shfl_xor_sync(0xffffffff, mx0, 1));
        mx0 = fmaxf(mx0, __shfl_xor_sync(0xffffffff, mx0, 2));
        mx1 = fmaxf(mx1, __shfl_xor_sync(0xffffffff, mx1, 1));
        mx1 = fmaxf(mx1, __shfl_xor_sync(0xffffffff, mx1, 2));
        float mn0 = fmaxf(m0, mx0), mn1 = fmaxf(m1, mx1);
        float cr0 = __expf(m0 - mn0), cr1 = __expf(m1 - mn1);
        m0 = mn0; m1 = mn1;
        l0 *= cr0; l1 *= cr1;
        #pragma unroll
        for (int d = 0; d < 8; ++d) {
            accO[d][0] *= cr0; accO[d][1] *= cr0;
            accO[d][2] *= cr1; accO[d][3] *= cr1;
        }

        // ---- P = exp(S-m) as bf16 hi/lo A-fragments ----
        uint32_t pah[4][4], pal[4][4];
        #pragma unroll
        for (int nt = 0; nt < 8; ++nt) {
            float p0 = __expf(sacc[nt][0] - mn0);
            float p1 = __expf(sacc[nt][1] - mn0);
            float p2 = __expf(sacc[nt][2] - mn1);
            float p3 = __expf(sacc[nt][3] - mn1);
            l0 += p0 + p1;
            l1 += p2 + p3;
            uint32_t h01, l01, h23, l23;
            split2(p0, p1, h01, l01);
            split2(p2, p3, h23, l23);
            int kt = nt >> 1;
            if ((nt & 1) == 0) {
                pah[kt][0] = h01; pah[kt][1] = h23;
                pal[kt][0] = l01; pal[kt][1] = l23;
            } else {
                pah[kt][2] = h01; pah[kt][3] = h23;
                pal[kt][2] = l01; pal[kt][3] = l23;
            }
        }

        // ---- O += P V ----
        const int mat = lane >> 3;
        const int rr  = lane & 7;
        #pragma unroll
        for (int kt = 0; kt < 4; ++kt) {
            #pragma unroll
            for (int pr = 0; pr < 4; ++pr) {
                uint32_t off = (uint32_t)((kt * 16 + rr + (mat & 1) * 8) * SA)
                             + (uint32_t)((pr * 16 + (mat >> 1) * 8) * 2);
                uint32_t vh[4], vl[4];
                ldmat4t(vh, uVh + off);
                mma16816(accO[2 * pr],     pah[kt], vh[0], vh[1]);
                mma16816(accO[2 * pr],     pal[kt], vh[0], vh[1]);
                mma16816(accO[2 * pr + 1], pah[kt], vh[2], vh[3]);
                mma16816(accO[2 * pr + 1], pal[kt], vh[2], vh[3]);
                ldmat4t(vl, uVl + off);
                mma16816(accO[2 * pr],     pah[kt], vl[0], vl[1]);
                mma16816(accO[2 * pr + 1], pah[kt], vl[2], vl[3]);
            }
        }
        __syncthreads();
    }

    // ---- finalize: write ctx as bf16 hi/lo ----
    l0 += __shfl_xor_sync(0xffffffff, l0, 1);
    l0 += __shfl_xor_sync(0xffffffff, l0, 2);
    l1 += __shfl_xor_sync(0xffffffff, l1, 1);
    l1 += __shfl_xor_sync(0xffffffff, l1, 2);
    float inv0 = 1.0f / l0, inv1 = 1.0f / l1;

    int q0 = qb * 64 + qrow;
    size_t base0 = ((size_t)b * SS + q0) * DD + h * DKK;
    size_t base1 = base0 + (size_t)8 * DD;
    #pragma unroll
    for (int d = 0; d < 8; ++d) {
        int col = d * 8 + 2 * t;
        uint32_t hi, lo;
        split2(accO[d][0] * inv0, accO[d][1] * inv0, hi, lo);
        *(uint32_t*)(g_chi + base0 + col) = hi;
        *(uint32_t*)(g_clo + base0 + col) = lo;
        split2(accO[d][2] * inv1, accO[d][3] * inv1, hi, lo);
        *(uint32_t*)(g_chi + base1 + col) = hi;
        *(uint32_t*)(g_clo + base1 + col) = lo;
    }
}

// ---------------------------------------------------------------------------
extern "C" void kernel_launch(void* const* d_in, const int* in_sizes, int n_in,
                              void* d_out, int out_size)
{
    (void)in_sizes; (void)n_in; (void)out_size;
    const float* Q  = (const float*)d_in[0];
    const float* K  = (const float*)d_in[1];
    const float* V  = (const float*)d_in[2];
    const float* Wq = (const float*)d_in[4];
    const float* Wk = (const float*)d_in[5];
    const float* Wv = (const float*)d_in[6];
    const float* Wo = (const float*)d_in[7];
    float* out = (float*)d_out;

    constexpr int GEMM_SMEM  = 2 * GBUF;      // 147456
    constexpr int FLASH_SMEM = FQ + 2 * FBUF; // 92160
    static bool attr_done = false;
    if (!attr_done) {
        cudaFuncSetAttribute(gemm_bf<0>,
                             cudaFuncAttributeMaxDynamicSharedMemorySize, GEMM_SMEM);
        cudaFuncSetAttribute(gemm_bf<1>,
                             cudaFuncAttributeMaxDynamicSharedMemorySize, GEMM_SMEM);
        cudaFuncSetAttribute(flash_tc,
                             cudaFuncAttributeMaxDynamicSharedMemorySize, FLASH_SMEM);
        attr_done = true;
    }

    conv_x<<<dim3(XN / 4 / 256, 1, 3), 256>>>(Q, K, V);
    conv_w<<<dim3(WN / 4 / 256, 1, 4), 256>>>(Wq, Wk, Wv, Wo);

    gemm_bf<0><<<dim3(DD / 128, (BB * SS) / 128, 3), 256, GEMM_SMEM>>>(nullptr);

    flash_tc<<<dim3(SS / 64, HH, BB), 128, FLASH_SMEM>>>();

    gemm_bf<1><<<dim3(DD / 128, (BB * SS) / 128, 1), 256, GEMM_SMEM>>>(out);
}